// round 6
// baseline (speedup 1.0000x reference)
#include <cuda_runtime.h>
#include <stdint.h>

#define NB_COUNT 32
#define DIM 128          // floats per row
#define VEC (DIM / 4)    // 32 float4 per row

__device__ float g_sink;  // prevents DCE of prefetch loads

// Prefetch/pin the table in L2: v8.b32 loads with evict_last set the lines'
// L2 eviction class so subsequent streaming traffic (indices, output) does
// not churn them out. First graph replay pays DRAM; later replays are L2 hits.
__global__ __launch_bounds__(256) void pin_table_kernel(
    const char* __restrict__ emb, long total_bytes)
{
    const long stride = (long)gridDim.x * blockDim.x * 32;
    float acc = 0.f;
    for (long off = ((long)blockIdx.x * blockDim.x + threadIdx.x) * 32;
         off < total_bytes; off += stride) {
        unsigned r0, r1, r2, r3, r4, r5, r6, r7;
        asm("ld.global.nc.L2::evict_last.v8.b32 {%0,%1,%2,%3,%4,%5,%6,%7}, [%8];"
            : "=r"(r0), "=r"(r1), "=r"(r2), "=r"(r3),
              "=r"(r4), "=r"(r5), "=r"(r6), "=r"(r7)
            : "l"(emb + off));
        acc += __uint_as_float(r0) + __uint_as_float(r7);
    }
    if (acc == 1.23456789e30f) g_sink = acc;  // never true; defeats DCE
}

// Index load: streaming (evict_first) — touched once per launch.
__device__ __forceinline__ int ld_idx_stream(const int* p) {
    int v;
    asm("ld.global.cs.s32 %0, [%1];" : "=r"(v) : "l"(p));
    return v;
}

// Output store: streaming — must not displace pinned table lines.
__device__ __forceinline__ void st_out_stream(float4* p, float4 v) {
    asm volatile("st.global.cs.v4.f32 [%0], {%1,%2,%3,%4};"
                 :: "l"(p), "f"(v.x), "f"(v.y), "f"(v.z), "f"(v.w));
}

// One warp per node. Lane l handles float4 column l. (R1 structure — best.)
__global__ __launch_bounds__(256) void sum_agg_kernel(
    const int* __restrict__ neighs,
    const float4* __restrict__ emb,   // [num_ids][32] float4
    float4* __restrict__ out,         // [node_count][32] float4
    int node_count)
{
    const int warp = (blockIdx.x * blockDim.x + threadIdx.x) >> 5;
    const int lane = threadIdx.x & 31;
    if (warp >= node_count) return;

    const int my_idx = ld_idx_stream(&neighs[(size_t)warp * NB_COUNT + lane]);

    float4 acc0 = make_float4(0.f, 0.f, 0.f, 0.f);
    float4 acc1 = make_float4(0.f, 0.f, 0.f, 0.f);

    #pragma unroll
    for (int j = 0; j < 16; ++j) {
        const int r0 = __shfl_sync(0xffffffffu, my_idx, 2 * j);
        const int r1 = __shfl_sync(0xffffffffu, my_idx, 2 * j + 1);
        const float4 v0 = __ldg(&emb[(size_t)r0 * VEC + lane]);
        const float4 v1 = __ldg(&emb[(size_t)r1 * VEC + lane]);
        acc0.x += v0.x; acc0.y += v0.y; acc0.z += v0.z; acc0.w += v0.w;
        acc1.x += v1.x; acc1.y += v1.y; acc1.z += v1.z; acc1.w += v1.w;
    }

    float4 r;
    r.x = acc0.x + acc1.x;
    r.y = acc0.y + acc1.y;
    r.z = acc0.z + acc1.z;
    r.w = acc0.w + acc1.w;
    st_out_stream(&out[(size_t)warp * VEC + lane], r);
}

extern "C" void kernel_launch(void* const* d_in, const int* in_sizes, int n_in,
                              void* d_out, int out_size)
{
    // metadata order: neighs (int32), node_count (int scalar), emb_table (f32)
    const int* neighs = (const int*)d_in[0];
    const float4* emb = (const float4*)d_in[2];
    float4* out = (float4*)d_out;

    const int node_count = out_size / DIM;       // out is [node_count, 128] f32
    const long table_bytes = (long)in_sizes[2] * 4;

    // Pin the embedding table in L2 (evict_last class), then gather.
    pin_table_kernel<<<296, 256>>>((const char*)emb, table_bytes);

    const int threads = 256;                      // 8 warps = 8 nodes per block
    const int blocks = (node_count * 32 + threads - 1) / threads;
    sum_agg_kernel<<<blocks, threads>>>(neighs, emb, out, node_count);
}

// round 7
// speedup vs baseline: 1.0894x; 1.0894x over previous
#include <cuda_runtime.h>
#include <stdint.h>

#define NB_COUNT 32
#define DIM 128          // floats per row
#define VEC (DIM / 4)    // 32 float4 per row

// One warp per node. Lane l handles float4 column l.
// __launch_bounds__(256, 8): force <=32 regs so 8 blocks (64 warps) fit per
// SM — the kernel is latency-bound (no pipe saturated), so resident-warp
// count is the lever.
__global__ __launch_bounds__(256, 8) void sum_agg_kernel(
    const int* __restrict__ neighs,
    const float4* __restrict__ emb,   // [num_ids][32] float4
    float4* __restrict__ out,         // [node_count][32] float4
    int node_count)
{
    const int warp = (blockIdx.x * blockDim.x + threadIdx.x) >> 5;
    const int lane = threadIdx.x & 31;
    if (warp >= node_count) return;

    // Coalesced index load: lane l gets neighbor l of this node.
    const int my_idx = neighs[(size_t)warp * NB_COUNT + lane];

    float4 acc0 = make_float4(0.f, 0.f, 0.f, 0.f);
    float4 acc1 = make_float4(0.f, 0.f, 0.f, 0.f);

    #pragma unroll
    for (int j = 0; j < 16; ++j) {
        const int r0 = __shfl_sync(0xffffffffu, my_idx, 2 * j);
        const int r1 = __shfl_sync(0xffffffffu, my_idx, 2 * j + 1);
        const float4 v0 = __ldg(&emb[(size_t)r0 * VEC + lane]);
        const float4 v1 = __ldg(&emb[(size_t)r1 * VEC + lane]);
        acc0.x += v0.x; acc0.y += v0.y; acc0.z += v0.z; acc0.w += v0.w;
        acc1.x += v1.x; acc1.y += v1.y; acc1.z += v1.z; acc1.w += v1.w;
    }

    float4 r;
    r.x = acc0.x + acc1.x;
    r.y = acc0.y + acc1.y;
    r.z = acc0.z + acc1.z;
    r.w = acc0.w + acc1.w;
    out[(size_t)warp * VEC + lane] = r;
}

extern "C" void kernel_launch(void* const* d_in, const int* in_sizes, int n_in,
                              void* d_out, int out_size)
{
    // metadata order: neighs (int32), node_count (int scalar), emb_table (f32)
    const int* neighs = (const int*)d_in[0];
    const float4* emb = (const float4*)d_in[2];
    float4* out = (float4*)d_out;

    const int node_count = out_size / DIM;   // out is [node_count, 128] f32

    const int threads = 256;                  // 8 warps = 8 nodes per block
    const int blocks = (node_count * 32 + threads - 1) / threads;

    sum_agg_kernel<<<blocks, threads>>>(neighs, emb, out, node_count);
}

// round 8
// speedup vs baseline: 1.1480x; 1.0538x over previous
#include <cuda_runtime.h>
#include <stdint.h>

#define NB_COUNT 32
#define DIM 128           // floats per row
#define VEC2 (DIM / 2)    // 64 float2 per row

// One warp per node, LDG.64 gathers.
// L1tex cost model per SM (43.2K line-fetches total):
//   LDG.128: 10.8K instr x (1.0 + 3*2.07) = 78K cyc   (within-LDG replays)
//   LDG.32 : 43.2K instr x 1.82 issue     = 78.6K cyc (LSU issue floor)
//   LDG.64 : 21.6K instr x (1.0 + 2.07)   = 66K cyc   <- sweet spot
// Lane l owns float2 columns l and l+32 (bytes [8l,8l+8) and [256+8l,...)).
__global__ __launch_bounds__(256, 8) void sum_agg_kernel(
    const int* __restrict__ neighs,
    const float2* __restrict__ emb,   // [num_ids][64] float2
    float2* __restrict__ out,         // [node_count][64] float2
    int node_count)
{
    const int warp = (blockIdx.x * blockDim.x + threadIdx.x) >> 5;
    const int lane = threadIdx.x & 31;
    if (warp >= node_count) return;

    // Coalesced index load: lane l gets neighbor l of this node.
    const int my_idx = neighs[(size_t)warp * NB_COUNT + lane];

    float ax0 = 0.f, ay0 = 0.f;   // column l
    float ax1 = 0.f, ay1 = 0.f;   // column l+32

    #pragma unroll
    for (int j = 0; j < NB_COUNT; ++j) {
        const int r = __shfl_sync(0xffffffffu, my_idx, j);
        const float2* row = emb + (size_t)r * VEC2 + lane;
        const float2 v0 = __ldg(row);        // LDG.64, lines 0-1 of the row
        const float2 v1 = __ldg(row + 32);   // LDG.64, lines 2-3 of the row
        ax0 += v0.x; ay0 += v0.y;
        ax1 += v1.x; ay1 += v1.y;
    }

    float2* o = out + (size_t)warp * VEC2 + lane;
    o[0]  = make_float2(ax0, ay0);
    o[32] = make_float2(ax1, ay1);
}

extern "C" void kernel_launch(void* const* d_in, const int* in_sizes, int n_in,
                              void* d_out, int out_size)
{
    // metadata order: neighs (int32), node_count (int scalar), emb_table (f32)
    const int* neighs = (const int*)d_in[0];
    const float2* emb = (const float2*)d_in[2];
    float2* out = (float2*)d_out;

    const int node_count = out_size / DIM;   // out is [node_count, 128] f32

    const int threads = 256;                  // 8 warps = 8 nodes per block
    const int blocks = (node_count * 32 + threads - 1) / threads;

    sum_agg_kernel<<<blocks, threads>>>(neighs, emb, out, node_count);
}